// round 7
// baseline (speedup 1.0000x reference)
#include <cuda_runtime.h>
#include <cuda_bf16.h>

#define BB 2
#define DD 10
#define HH 512
#define WW 512

__device__ __forceinline__ float4 fmax4(float4 a, float4 b) {
    return make_float4(fmaxf(a.x, b.x), fmaxf(a.y, b.y), fmaxf(a.z, b.z), fmaxf(a.w, b.w));
}

// Select component j (0..3) of (a,b,c,d). ISETPs hoisted/shared by the compiler.
__device__ __forceinline__ float sel4(float a, float b, float c, float d, int j) {
    float r = a;
    r = (j == 1) ? b : r;
    r = (j == 2) ? c : r;
    r = (j == 3) ? d : r;
    return r;
}

// 3x3 Newton solve at a detected maximum. Same algebra as the verified kernels.
__device__ __forceinline__ void newton_step(
    float cc,
    float a4, float c4,                    // row4 (d,h)     at j, j+2
    float a3, float b3, float c3,          // row3 (d,h-1)   at j, j+1, j+2
    float a5, float b5, float c5,          // row5 (d,h+1)
    float a1, float b1v, float c1,         // row1 (d-1,h)
    float a7, float b7, float c7,          // row7 (d+1,h)
    float e0, float e2, float e6, float e8,// rows 0,2,6,8 at j+1
    float& dx0, float& dx1, float& dx2, float& yv)
{
    const float gx = 0.5f * (c4 - a4);
    const float gy = 0.5f * (b5 - b3);
    const float gs = 0.5f * (b7 - b1v);

    const float dxx = a4 + c4 - 2.0f * cc;
    const float dyy = b3 + b5 - 2.0f * cc;
    const float dss = b1v + b7 - 2.0f * cc;
    const float dxy = 0.25f * (a3 + c5 - a5 - c3);
    const float dys = 0.25f * (e0 + e8 - e6 - e2);
    const float dxs = 0.25f * (a1 + c7 - a7 - c1);

    const float h00 = dxx, h01 = dxy, h02 = dxs;
    const float h10 = dxy, h11 = dyy, h12 = dys;
    const float h20 = dxs, h21 = dys, h22 = dss;
    const float b0 = gx, b1 = gy, b2 = gs;

    const float c00 = h11 * h22 - h12 * h21;
    const float c01 = h10 * h22 - h12 * h20;
    const float c02 = h10 * h21 - h11 * h20;
    const float det = h00 * c00 - h01 * c01 + h02 * c02;

    const float t1 = b1 * h22 - h12 * b2;
    const float t2 = b1 * h21 - h11 * b2;
    const float t3 = h10 * b2 - b1 * h20;

    const float inv = 1.0f / det;
    const float sx = (b0 * c00 - h01 * t1 + h02 * t2) * inv;
    const float sy = (h00 * t1 - b0 * c01 + h02 * t3) * inv;
    const float ss = (h00 * (h11 * b2 - h21 * b1) - h01 * t3 + b0 * c02) * inv;

    float d0 = -sx, d1 = -sy, d2 = -ss;
    const float far = fmaxf(fmaxf(fabsf(d0), fabsf(d1)), fabsf(d2));
    if (far > 0.7f) { d0 = 0.0f; d1 = 0.0f; d2 = 0.0f; }

    dx0 = d0; dx1 = d1; dx2 = d2;
    yv = cc + 0.5f * (gx * d0 + gy * d1 + gs * d2) + 10.0f;
}

__global__ __launch_bounds__(256, 4)   // 64 regs, 4 CTAs/SM
void quadinterp3d_kernel(const float* __restrict__ x, float* __restrict__ out) {
    // Block = 2 complete W-rows of 128 threads each; neighbors are adjacent tids.
    __shared__ float sCmX[256], sCmW[256], sV4X[256], sV4W[256];

    const int tid  = threadIdx.x;
    const int gid  = blockIdx.x * 256 + tid;
    const int w4 = gid & 127;            // 0..127, consecutive within a half-block row
    const int h  = (gid >> 7) & 511;
    const int t  = gid >> 16;            // 0..19 (B*D)
    const int d  = t % DD;
    const int b  = t / DD;
    const int w0 = w4 << 2;

    // Clamped stencil offsets via predicated deltas (replicate padding)
    const int off4 = (d * HH + h) * WW;
    const int dym = (h > 0)      ? WW : 0;
    const int dyp = (h < HH - 1) ? WW : 0;
    const int dzm = (d > 0)      ? HH * WW : 0;
    const int dzp = (d < DD - 1) ? HH * WW : 0;

    int off[9];
    off[0] = off4 - dzm - dym;  off[1] = off4 - dzm;  off[2] = off4 - dzm + dyp;
    off[3] = off4 - dym;        off[4] = off4;        off[5] = off4 + dyp;
    off[6] = off4 + dzp - dym;  off[7] = off4 + dzp;  off[8] = off4 + dzp + dyp;

    const float* __restrict__ base = x + (size_t)b * DD * HH * WW;

    // Batched independent loads: one aligned float4 per stencil row (MLP=9)
    float4 v[9];
    #pragma unroll
    for (int r = 0; r < 9; r++)
        v[r] = *reinterpret_cast<const float4*>(base + off[r] + w0);

    // Column max of the 8 non-center rows
    float4 cm = fmax4(fmax4(v[0], v[1]), fmax4(v[2], v[3]));
    cm = fmax4(cm, fmax4(fmax4(v[5], v[6]), fmax4(v[7], v[8])));

    // Block-level edge exchange
    sCmX[tid] = cm.x;  sCmW[tid] = cm.w;
    sV4X[tid] = v[4].x; sV4W[tid] = v[4].w;
    __syncthreads();

    const bool atL = (w4 == 0);
    const bool atR = (w4 == 127);
    const float cmL = atL ? cm.x   : sCmW[tid - 1];
    const float cmR = atR ? cm.w   : sCmX[tid + 1];
    const float r4l = atL ? v[4].x : sV4W[tid - 1];
    const float r4r = atR ? v[4].w : sV4X[tid + 1];

    // Windowed max over [cmL, cm.x, cm.y, cm.z, cm.w, cmR]
    const float p01 = fmaxf(cmL,  cm.x);
    const float p12 = fmaxf(cm.x, cm.y);
    const float p23 = fmaxf(cm.y, cm.z);
    const float p34 = fmaxf(cm.z, cm.w);
    const float win0 = fmaxf(p01, cm.y);
    const float win1 = fmaxf(p12, cm.z);
    const float win2 = fmaxf(p23, cm.w);
    const float win3 = fmaxf(p34, cmR);

    // Center-row contribution (excludes the center element itself)
    const float u0 = r4l, u1 = v[4].x, u2 = v[4].y, u3 = v[4].z, u4 = v[4].w, u5 = r4r;
    const float nm0 = fmaxf(fmaxf(win0, fmaxf(u0, u2)), 0.0f);
    const float nm1 = fmaxf(fmaxf(win1, fmaxf(u1, u3)), 0.0f);
    const float nm2 = fmaxf(fmaxf(win2, fmaxf(u2, u4)), 0.0f);
    const float nm3 = fmaxf(fmaxf(win3, fmaxf(u3, u5)), 0.0f);

    float A0 = 0.f, B0 = 0.f, C0 = 0.f, y0 = u1;
    float A1 = 0.f, B1 = 0.f, C1 = 0.f, y1 = u2;
    float A2 = 0.f, B2 = 0.f, C2 = 0.f, y2 = u3;
    float A3 = 0.f, B3 = 0.f, C3 = 0.f, y3 = u4;

    // Per-lane maxima bitmask (adjacent voxels can't both be strict maxima,
    // so popcount is almost always 0 or 1; >=2 only for non-adjacent pairs ~0.4%)
    unsigned mm = (u1 > nm0 ? 1u : 0u) | (u2 > nm1 ? 2u : 0u)
                | (u3 > nm2 ? 4u : 0u) | (u4 > nm3 ? 8u : 0u);

    const int wl = atL ? 0 : (w0 - 1);
    const int wr = atR ? (WW - 1) : (w0 + 4);

    // Single-pass Newton: one warp-uniform loop, dynamic j per lane.
    while (__any_sync(0xffffffffu, mm)) {
        const bool active = (mm != 0u);
        const int  jj = active ? (__ffs(mm) - 1) : 0;

        // Edge values only needed for jj==0 (left) / jj==3 (right); predicated loads (L1 hits)
        const bool needL = active && (jj == 0);
        const bool needR = active && (jj == 3);
        const float eL1 = needL ? __ldg(base + off[1] + wl) : 0.0f;
        const float eL3 = needL ? __ldg(base + off[3] + wl) : 0.0f;
        const float eL5 = needL ? __ldg(base + off[5] + wl) : 0.0f;
        const float eL7 = needL ? __ldg(base + off[7] + wl) : 0.0f;
        const float eR1 = needR ? __ldg(base + off[1] + wr) : 0.0f;
        const float eR3 = needR ? __ldg(base + off[3] + wr) : 0.0f;
        const float eR5 = needR ? __ldg(base + off[5] + wr) : 0.0f;
        const float eR7 = needR ? __ldg(base + off[7] + wr) : 0.0f;

        // Gather the 19 stencil inputs for this lane's j
        const float cc = sel4(u1, u2, u3, u4, jj);
        const float a4 = sel4(u0, u1, u2, u3, jj);
        const float c4 = sel4(u2, u3, u4, u5, jj);

        const float a3 = sel4(eL3, v[3].x, v[3].y, v[3].z, jj);
        const float b3 = sel4(v[3].x, v[3].y, v[3].z, v[3].w, jj);
        const float c3 = sel4(v[3].y, v[3].z, v[3].w, eR3, jj);

        const float a5 = sel4(eL5, v[5].x, v[5].y, v[5].z, jj);
        const float b5 = sel4(v[5].x, v[5].y, v[5].z, v[5].w, jj);
        const float c5 = sel4(v[5].y, v[5].z, v[5].w, eR5, jj);

        const float a1 = sel4(eL1, v[1].x, v[1].y, v[1].z, jj);
        const float b1 = sel4(v[1].x, v[1].y, v[1].z, v[1].w, jj);
        const float c1 = sel4(v[1].y, v[1].z, v[1].w, eR1, jj);

        const float a7 = sel4(eL7, v[7].x, v[7].y, v[7].z, jj);
        const float b7 = sel4(v[7].x, v[7].y, v[7].z, v[7].w, jj);
        const float c7 = sel4(v[7].y, v[7].z, v[7].w, eR7, jj);

        const float e0 = sel4(v[0].x, v[0].y, v[0].z, v[0].w, jj);
        const float e2 = sel4(v[2].x, v[2].y, v[2].z, v[2].w, jj);
        const float e6 = sel4(v[6].x, v[6].y, v[6].z, v[6].w, jj);
        const float e8 = sel4(v[8].x, v[8].y, v[8].z, v[8].w, jj);

        float rA, rB, rC, ry;
        newton_step(cc, a4, c4, a3, b3, c3, a5, b5, c5,
                    a1, b1, c1, a7, b7, c7, e0, e2, e6, e8,
                    rA, rB, rC, ry);

        if (active) {
            if      (jj == 0) { A0 = rA; B0 = rB; C0 = rC; y0 = ry; }
            else if (jj == 1) { A1 = rA; B1 = rB; C1 = rC; y1 = ry; }
            else if (jj == 2) { A2 = rA; B2 = rB; C2 = rC; y2 = ry; }
            else              { A3 = rA; B3 = rB; C3 = rC; y3 = ry; }
            mm &= (mm - 1u);
        }
    }

    // Coalesced float4 stores: coords (B,3,D,H,W) then y (B,D,H,W)
    const size_t plsz = (size_t)DD * HH * WW;
    const size_t inner = (size_t)off4 + w0;
    const float fd = (float)d, fh = (float)h, fw = (float)w0;
    *reinterpret_cast<float4*>(out + (size_t)(b * 3 + 0) * plsz + inner) =
        make_float4(fd + C0, fd + C1, fd + C2, fd + C3);
    *reinterpret_cast<float4*>(out + (size_t)(b * 3 + 1) * plsz + inner) =
        make_float4(fh + B0, fh + B1, fh + B2, fh + B3);
    *reinterpret_cast<float4*>(out + (size_t)(b * 3 + 2) * plsz + inner) =
        make_float4(fw + A0, fw + 1.0f + A1, fw + 2.0f + A2, fw + 3.0f + A3);
    *reinterpret_cast<float4*>(out + (size_t)BB * 3 * plsz + (size_t)b * plsz + inner) =
        make_float4(y0, y1, y2, y3);
}

extern "C" void kernel_launch(void* const* d_in, const int* in_sizes, int n_in,
                              void* d_out, int out_size) {
    const float* x = (const float*)d_in[0];
    float* out = (float*)d_out;
    const int total_threads = BB * DD * HH * (WW / 4);   // 1,310,720
    const int block = 256;
    const int grid = total_threads / block;              // 5,120
    quadinterp3d_kernel<<<grid, block>>>(x, out);
}

// round 8
// speedup vs baseline: 1.4148x; 1.4148x over previous
#include <cuda_runtime.h>
#include <cuda_bf16.h>

#define BB 2
#define DD 10
#define HH 512
#define WW 512

__device__ __forceinline__ float4 fmax4(float4 a, float4 b) {
    return make_float4(fmaxf(a.x, b.x), fmaxf(a.y, b.y), fmaxf(a.z, b.z), fmaxf(a.w, b.w));
}

// Select component j (0..3) of (a,b,c,d).
__device__ __forceinline__ float sel4(float a, float b, float c, float d, int j) {
    float r = a;
    r = (j == 1) ? b : r;
    r = (j == 2) ? c : r;
    r = (j == 3) ? d : r;
    return r;
}

__global__ __launch_bounds__(256, 4)   // 64 regs, 4 CTAs/SM
void quadinterp3d_kernel(const float* __restrict__ x, float* __restrict__ out) {
    // Block = 2 complete W-rows of 128 threads each; neighbors are adjacent tids.
    __shared__ float sCmX[256], sCmW[256], sV4X[256], sV4W[256];

    const int tid  = threadIdx.x;
    const int gid  = blockIdx.x * 256 + tid;
    const int w4 = gid & 127;            // 0..127, consecutive within a half-block row
    const int h  = (gid >> 7) & 511;
    const int t  = gid >> 16;            // 0..19 (B*D)
    const int d  = t % DD;
    const int b  = t / DD;
    const int w0 = w4 << 2;

    // Clamped stencil offsets via predicated deltas (replicate padding)
    const int off4 = (d * HH + h) * WW;
    const int dym = (h > 0)      ? WW : 0;
    const int dyp = (h < HH - 1) ? WW : 0;
    const int dzm = (d > 0)      ? HH * WW : 0;
    const int dzp = (d < DD - 1) ? HH * WW : 0;

    int off[9];
    off[0] = off4 - dzm - dym;  off[1] = off4 - dzm;  off[2] = off4 - dzm + dyp;
    off[3] = off4 - dym;        off[4] = off4;        off[5] = off4 + dyp;
    off[6] = off4 + dzp - dym;  off[7] = off4 + dzp;  off[8] = off4 + dzp + dyp;

    const float* __restrict__ base = x + (size_t)b * DD * HH * WW;

    // Batched independent loads: one aligned float4 per stencil row (MLP=9)
    float4 v[9];
    #pragma unroll
    for (int r = 0; r < 9; r++)
        v[r] = *reinterpret_cast<const float4*>(base + off[r] + w0);

    // Column max of the 8 non-center rows
    float4 cm = fmax4(fmax4(v[0], v[1]), fmax4(v[2], v[3]));
    cm = fmax4(cm, fmax4(fmax4(v[5], v[6]), fmax4(v[7], v[8])));

    // Block-level edge exchange
    sCmX[tid] = cm.x;  sCmW[tid] = cm.w;
    sV4X[tid] = v[4].x; sV4W[tid] = v[4].w;
    __syncthreads();

    const bool atL = (w4 == 0);
    const bool atR = (w4 == 127);
    const float cmL = atL ? cm.x   : sCmW[tid - 1];
    const float cmR = atR ? cm.w   : sCmX[tid + 1];
    const float r4l = atL ? v[4].x : sV4W[tid - 1];
    const float r4r = atR ? v[4].w : sV4X[tid + 1];

    // Windowed max over [cmL, cm.x, cm.y, cm.z, cm.w, cmR]
    const float p01 = fmaxf(cmL,  cm.x);
    const float p12 = fmaxf(cm.x, cm.y);
    const float p23 = fmaxf(cm.y, cm.z);
    const float p34 = fmaxf(cm.z, cm.w);
    const float win0 = fmaxf(p01, cm.y);
    const float win1 = fmaxf(p12, cm.z);
    const float win2 = fmaxf(p23, cm.w);
    const float win3 = fmaxf(p34, cmR);

    // Center-row contribution (excludes the center element itself)
    const float u0 = r4l, u5 = r4r;
    const float nm0 = fmaxf(fmaxf(win0, fmaxf(u0,     v[4].y)), 0.0f);
    const float nm1 = fmaxf(fmaxf(win1, fmaxf(v[4].x, v[4].z)), 0.0f);
    const float nm2 = fmaxf(fmaxf(win2, fmaxf(v[4].y, v[4].w)), 0.0f);
    const float nm3 = fmaxf(fmaxf(win3, fmaxf(v[4].z, u5)),     0.0f);

    // Per-lane maxima bitmask
    unsigned mm = (v[4].x > nm0 ? 1u : 0u) | (v[4].y > nm1 ? 2u : 0u)
                | (v[4].z > nm2 ? 4u : 0u) | (v[4].w > nm3 ? 8u : 0u);

    // ---- Default stores FIRST (coords = grid, y = x). Maxima overwrite below. ----
    const size_t plsz = (size_t)DD * HH * WW;
    const size_t inner = (size_t)off4 + w0;
    float* const o0 = out + (size_t)(b * 3 + 0) * plsz + inner;
    float* const o1 = out + (size_t)(b * 3 + 1) * plsz + inner;
    float* const o2 = out + (size_t)(b * 3 + 2) * plsz + inner;
    float* const oy = out + (size_t)BB * 3 * plsz + (size_t)b * plsz + inner;
    const float fd = (float)d, fh = (float)h, fw = (float)w0;
    *reinterpret_cast<float4*>(o0) = make_float4(fd, fd, fd, fd);
    *reinterpret_cast<float4*>(o1) = make_float4(fh, fh, fh, fh);
    *reinterpret_cast<float4*>(o2) = make_float4(fw, fw + 1.0f, fw + 2.0f, fw + 3.0f);
    *reinterpret_cast<float4*>(oy) = v[4];

    const int wl = atL ? 0 : (w0 - 1);
    const int wr = atR ? (WW - 1) : (w0 + 4);

    // ---- Single-pass Newton: one warp-uniform loop, dynamic j per lane,
    //      direct scattered stores (same thread+address: program order wins). ----
    while (__any_sync(0xffffffffu, mm)) {
        const bool active = (mm != 0u);
        const int  jj = active ? (__ffs(mm) - 1) : 0;

        // Edge column loads only when jj==0 (left) or jj==3 (right); L1 hits, rare.
        const bool edge = active && ((jj == 0) | (jj == 3));
        const int  wc = (jj == 0) ? wl : wr;
        const float e1 = edge ? __ldg(base + off[1] + wc) : 0.0f;
        const float e3 = edge ? __ldg(base + off[3] + wc) : 0.0f;
        const float e5 = edge ? __ldg(base + off[5] + wc) : 0.0f;
        const float e7 = edge ? __ldg(base + off[7] + wc) : 0.0f;

        // Gather the 19 stencil inputs for this lane's j
        const float cc = sel4(v[4].x, v[4].y, v[4].z, v[4].w, jj);
        const float a4 = sel4(u0,     v[4].x, v[4].y, v[4].z, jj);
        const float c4 = sel4(v[4].y, v[4].z, v[4].w, u5,     jj);

        const float a3 = sel4(e3, v[3].x, v[3].y, v[3].z, jj);
        const float b3 = sel4(v[3].x, v[3].y, v[3].z, v[3].w, jj);
        const float c3 = sel4(v[3].y, v[3].z, v[3].w, e3, jj);

        const float a5 = sel4(e5, v[5].x, v[5].y, v[5].z, jj);
        const float b5 = sel4(v[5].x, v[5].y, v[5].z, v[5].w, jj);
        const float c5 = sel4(v[5].y, v[5].z, v[5].w, e5, jj);

        const float a1 = sel4(e1, v[1].x, v[1].y, v[1].z, jj);
        const float b1 = sel4(v[1].x, v[1].y, v[1].z, v[1].w, jj);
        const float c1 = sel4(v[1].y, v[1].z, v[1].w, e1, jj);

        const float a7 = sel4(e7, v[7].x, v[7].y, v[7].z, jj);
        const float b7 = sel4(v[7].x, v[7].y, v[7].z, v[7].w, jj);
        const float c7 = sel4(v[7].y, v[7].z, v[7].w, e7, jj);

        const float e0v = sel4(v[0].x, v[0].y, v[0].z, v[0].w, jj);
        const float e2v = sel4(v[2].x, v[2].y, v[2].z, v[2].w, jj);
        const float e6v = sel4(v[6].x, v[6].y, v[6].z, v[6].w, jj);
        const float e8v = sel4(v[8].x, v[8].y, v[8].z, v[8].w, jj);

        // Newton solve (same algebra as the verified kernels)
        const float gx = 0.5f * (c4 - a4);
        const float gy = 0.5f * (b5 - b3);
        const float gs = 0.5f * (b7 - b1);

        const float h00 = a4 + c4 - 2.0f * cc;
        const float h11 = b3 + b5 - 2.0f * cc;
        const float h22 = b1 + b7 - 2.0f * cc;
        const float h01 = 0.25f * (a3 + c5 - a5 - c3);
        const float h12 = 0.25f * (e0v + e8v - e6v - e2v);
        const float h02 = 0.25f * (a1 + c7 - a7 - c1);

        const float c00 = h11 * h22 - h12 * h12;
        const float c01 = h01 * h22 - h12 * h02;
        const float c02 = h01 * h12 - h11 * h02;
        const float det = h00 * c00 - h01 * c01 + h02 * c02;

        const float t1 = gy * h22 - h12 * gs;
        const float t2 = gy * h12 - h11 * gs;
        const float t3 = h01 * gs - gy * h02;

        const float inv = 1.0f / det;
        const float sx = (gx * c00 - h01 * t1 + h02 * t2) * inv;
        const float sy = (h00 * t1 - gx * c01 + h02 * t3) * inv;
        const float ss = (h00 * (h11 * gs - h12 * gy) - h01 * t3 + gx * c02) * inv;

        float d0 = -sx, d1 = -sy, d2 = -ss;
        const float far = fmaxf(fmaxf(fabsf(d0), fabsf(d1)), fabsf(d2));
        if (far > 0.7f) { d0 = 0.0f; d1 = 0.0f; d2 = 0.0f; }

        const float ry = cc + 0.5f * (gx * d0 + gy * d1 + gs * d2) + 10.0f;

        if (active) {
            o0[jj] = fd + d2;
            o1[jj] = fh + d1;
            o2[jj] = fw + (float)jj + d0;
            oy[jj] = ry;
            mm &= (mm - 1u);
        }
    }
}

extern "C" void kernel_launch(void* const* d_in, const int* in_sizes, int n_in,
                              void* d_out, int out_size) {
    const float* x = (const float*)d_in[0];
    float* out = (float*)d_out;
    const int total_threads = BB * DD * HH * (WW / 4);   // 1,310,720
    const int block = 256;
    const int grid = total_threads / block;              // 5,120
    quadinterp3d_kernel<<<grid, block>>>(x, out);
}

// round 9
// speedup vs baseline: 1.5233x; 1.0767x over previous
#include <cuda_runtime.h>
#include <cuda_bf16.h>

#define BB 2
#define DD 10
#define HH 512
#define WW 512
#define HW (HH * WW)

__device__ __forceinline__ float4 fmax4(float4 a, float4 b) {
    return make_float4(fmaxf(a.x, b.x), fmaxf(a.y, b.y), fmaxf(a.z, b.z), fmaxf(a.w, b.w));
}

// 3x3 Newton solve at a detected maximum. Same algebra as the verified kernels.
__device__ __forceinline__ void newton_step(
    float cc,
    float a4, float c4,                    // row4 (d,h)     at j, j+2
    float a3, float b3, float c3,          // row3 (d,h-1)   at j, j+1, j+2
    float a5, float b5, float c5,          // row5 (d,h+1)
    float a1, float b1v, float c1,         // row1 (d-1,h)
    float a7, float b7, float c7,          // row7 (d+1,h)
    float e0, float e2, float e6, float e8,// rows 0,2,6,8 at j+1
    float& dx0, float& dx1, float& dx2, float& yv)
{
    const float gx = 0.5f * (c4 - a4);
    const float gy = 0.5f * (b5 - b3);
    const float gs = 0.5f * (b7 - b1v);

    const float h00 = a4 + c4 - 2.0f * cc;
    const float h11 = b3 + b5 - 2.0f * cc;
    const float h22 = b1v + b7 - 2.0f * cc;
    const float h01 = 0.25f * (a3 + c5 - a5 - c3);
    const float h12 = 0.25f * (e0 + e8 - e6 - e2);
    const float h02 = 0.25f * (a1 + c7 - a7 - c1);

    const float c00 = h11 * h22 - h12 * h12;
    const float c01 = h01 * h22 - h12 * h02;
    const float c02 = h01 * h12 - h11 * h02;
    const float det = h00 * c00 - h01 * c01 + h02 * c02;

    const float t1 = gy * h22 - h12 * gs;
    const float t2 = gy * h12 - h11 * gs;
    const float t3 = h01 * gs - gy * h02;

    const float inv = 1.0f / det;
    const float sx = (gx * c00 - h01 * t1 + h02 * t2) * inv;
    const float sy = (h00 * t1 - gx * c01 + h02 * t3) * inv;
    const float ss = (h00 * (h11 * gs - h12 * gy) - h01 * t3 + gx * c02) * inv;

    float d0 = -sx, d1 = -sy, d2 = -ss;
    const float far = fmaxf(fmaxf(fabsf(d0), fabsf(d1)), fabsf(d2));
    if (far > 0.7f) { d0 = 0.0f; d1 = 0.0f; d2 = 0.0f; }

    dx0 = d0; dx1 = d1; dx2 = d2;
    yv = cc + 0.5f * (gx * d0 + gy * d1 + gs * d2) + 10.0f;
}

__global__ __launch_bounds__(256, 4)   // 64 regs, 4 CTAs/SM
void quadinterp3d_kernel(const float* __restrict__ x, float* __restrict__ out) {
    // Block = 2 complete W-rows of 128 threads each; neighbors are adjacent tids.
    __shared__ float sCmX[256], sCmW[256], sV4X[256], sV4W[256];

    const int tid  = threadIdx.x;
    const int gid  = blockIdx.x * 256 + tid;
    const int w4 = gid & 127;            // 0..127, consecutive within a half-block row
    const int h  = (gid >> 7) & 511;
    const int t  = gid >> 16;            // 0..19 (B*D)
    const int d  = t % DD;
    const int b  = t / DD;
    const int w0 = w4 << 2;

    const int off4 = (d * HH + h) * WW;
    const float* __restrict__ base = x + (size_t)b * DD * HW;
    const float* __restrict__ pc = base + off4 + w0;   // single 64-bit base

    // Row deltas (replicate padding via clamped deltas)
    const int dym = (h > 0)      ? WW : 0;
    const int dyp = (h < HH - 1) ? WW : 0;
    const int dzm = (d > 0)      ? HW : 0;
    const int dzp = (d < DD - 1) ? HW : 0;

    float4 v[9];
    // Warp-uniform branch (h, d constant across the warp); interior = 78% of warps.
    if (dym & dyp & dzm & dzp) {
        // Compile-time immediate offsets folded into [R+imm] addressing
        v[0] = *reinterpret_cast<const float4*>(pc - HW - WW);
        v[1] = *reinterpret_cast<const float4*>(pc - HW);
        v[2] = *reinterpret_cast<const float4*>(pc - HW + WW);
        v[3] = *reinterpret_cast<const float4*>(pc - WW);
        v[4] = *reinterpret_cast<const float4*>(pc);
        v[5] = *reinterpret_cast<const float4*>(pc + WW);
        v[6] = *reinterpret_cast<const float4*>(pc + HW - WW);
        v[7] = *reinterpret_cast<const float4*>(pc + HW);
        v[8] = *reinterpret_cast<const float4*>(pc + HW + WW);
    } else {
        v[0] = *reinterpret_cast<const float4*>(pc - dzm - dym);
        v[1] = *reinterpret_cast<const float4*>(pc - dzm);
        v[2] = *reinterpret_cast<const float4*>(pc - dzm + dyp);
        v[3] = *reinterpret_cast<const float4*>(pc - dym);
        v[4] = *reinterpret_cast<const float4*>(pc);
        v[5] = *reinterpret_cast<const float4*>(pc + dyp);
        v[6] = *reinterpret_cast<const float4*>(pc + dzp - dym);
        v[7] = *reinterpret_cast<const float4*>(pc + dzp);
        v[8] = *reinterpret_cast<const float4*>(pc + dzp + dyp);
    }

    // Column max of the 8 non-center rows
    float4 cm = fmax4(fmax4(v[0], v[1]), fmax4(v[2], v[3]));
    cm = fmax4(cm, fmax4(fmax4(v[5], v[6]), fmax4(v[7], v[8])));

    // Block-level edge exchange
    sCmX[tid] = cm.x;  sCmW[tid] = cm.w;
    sV4X[tid] = v[4].x; sV4W[tid] = v[4].w;
    __syncthreads();

    const bool atL = (w4 == 0);
    const bool atR = (w4 == 127);
    const float cmL = atL ? cm.x   : sCmW[tid - 1];
    const float cmR = atR ? cm.w   : sCmX[tid + 1];
    const float u0  = atL ? v[4].x : sV4W[tid - 1];
    const float u5  = atR ? v[4].w : sV4X[tid + 1];

    // Windowed max over [cmL, cm.x, cm.y, cm.z, cm.w, cmR]
    const float p01 = fmaxf(cmL,  cm.x);
    const float p12 = fmaxf(cm.x, cm.y);
    const float p23 = fmaxf(cm.y, cm.z);
    const float p34 = fmaxf(cm.z, cm.w);
    const float win0 = fmaxf(p01, cm.y);
    const float win1 = fmaxf(p12, cm.z);
    const float win2 = fmaxf(p23, cm.w);
    const float win3 = fmaxf(p34, cmR);

    // Center-row contribution (excludes the center element itself)
    const float nm0 = fmaxf(fmaxf(win0, fmaxf(u0,     v[4].y)), 0.0f);
    const float nm1 = fmaxf(fmaxf(win1, fmaxf(v[4].x, v[4].z)), 0.0f);
    const float nm2 = fmaxf(fmaxf(win2, fmaxf(v[4].y, v[4].w)), 0.0f);
    const float nm3 = fmaxf(fmaxf(win3, fmaxf(v[4].z, u5)),     0.0f);

    const bool m0 = v[4].x > nm0;
    const bool m1 = v[4].y > nm1;
    const bool m2 = v[4].z > nm2;
    const bool m3 = v[4].w > nm3;

    // ---- Default stores FIRST (coords = grid, y = x). Maxima overwrite below
    //      (same thread, same address: program order wins). ----
    const size_t plsz = (size_t)DD * HW;
    const size_t inner = (size_t)off4 + w0;
    float* const po0 = out + (size_t)(b * 3 + 0) * plsz + inner;
    float* const po1 = out + (size_t)(b * 3 + 1) * plsz + inner;
    float* const po2 = out + (size_t)(b * 3 + 2) * plsz + inner;
    float* const poy = out + (size_t)BB * 3 * plsz + (size_t)b * plsz + inner;
    const float fd = (float)d, fh = (float)h, fw = (float)w0;
    *reinterpret_cast<float4*>(po0) = make_float4(fd, fd, fd, fd);
    *reinterpret_cast<float4*>(po1) = make_float4(fh, fh, fh, fh);
    *reinterpret_cast<float4*>(po2) = make_float4(fw, fw + 1.0f, fw + 2.0f, fw + 3.0f);
    *reinterpret_cast<float4*>(poy) = v[4];

    // Rebased edge offsets for the rare Newton loads
    const int dwl = atL ? 0 : -1;   // (wl - w0)
    const int dwr = atR ? 3 : 4;    // (wr - w0)
    const int o1r = -dzm, o3r = -dym, o5r = dyp, o7r = dzp;

    float dx0, dx1, dx2, yv;

    // Heavy path (~3.7% of voxels): 4 branches, direct scattered stores.
    if (m0) {
        const float a1 = __ldg(pc + o1r + dwl);
        const float a3 = __ldg(pc + o3r + dwl);
        const float a5 = __ldg(pc + o5r + dwl);
        const float a7 = __ldg(pc + o7r + dwl);
        newton_step(v[4].x, u0, v[4].y,
                    a3, v[3].x, v[3].y,
                    a5, v[5].x, v[5].y,
                    a1, v[1].x, v[1].y,
                    a7, v[7].x, v[7].y,
                    v[0].x, v[2].x, v[6].x, v[8].x,
                    dx0, dx1, dx2, yv);
        po0[0] = fd + dx2;  po1[0] = fh + dx1;  po2[0] = fw + dx0;  poy[0] = yv;
    }
    if (m1) {
        newton_step(v[4].y, v[4].x, v[4].z,
                    v[3].x, v[3].y, v[3].z,
                    v[5].x, v[5].y, v[5].z,
                    v[1].x, v[1].y, v[1].z,
                    v[7].x, v[7].y, v[7].z,
                    v[0].y, v[2].y, v[6].y, v[8].y,
                    dx0, dx1, dx2, yv);
        po0[1] = fd + dx2;  po1[1] = fh + dx1;  po2[1] = fw + 1.0f + dx0;  poy[1] = yv;
    }
    if (m2) {
        newton_step(v[4].z, v[4].y, v[4].w,
                    v[3].y, v[3].z, v[3].w,
                    v[5].y, v[5].z, v[5].w,
                    v[1].y, v[1].z, v[1].w,
                    v[7].y, v[7].z, v[7].w,
                    v[0].z, v[2].z, v[6].z, v[8].z,
                    dx0, dx1, dx2, yv);
        po0[2] = fd + dx2;  po1[2] = fh + dx1;  po2[2] = fw + 2.0f + dx0;  poy[2] = yv;
    }
    if (m3) {
        const float c1 = __ldg(pc + o1r + dwr);
        const float c3 = __ldg(pc + o3r + dwr);
        const float c5 = __ldg(pc + o5r + dwr);
        const float c7 = __ldg(pc + o7r + dwr);
        newton_step(v[4].w, v[4].z, u5,
                    v[3].z, v[3].w, c3,
                    v[5].z, v[5].w, c5,
                    v[1].z, v[1].w, c1,
                    v[7].z, v[7].w, c7,
                    v[0].w, v[2].w, v[6].w, v[8].w,
                    dx0, dx1, dx2, yv);
        po0[3] = fd + dx2;  po1[3] = fh + dx1;  po2[3] = fw + 3.0f + dx0;  poy[3] = yv;
    }
}

extern "C" void kernel_launch(void* const* d_in, const int* in_sizes, int n_in,
                              void* d_out, int out_size) {
    const float* x = (const float*)d_in[0];
    float* out = (float*)d_out;
    const int total_threads = BB * DD * HH * (WW / 4);   // 1,310,720
    const int block = 256;
    const int grid = total_threads / block;              // 5,120
    quadinterp3d_kernel<<<grid, block>>>(x, out);
}

// round 10
// speedup vs baseline: 1.6975x; 1.1143x over previous
#include <cuda_runtime.h>
#include <cuda_bf16.h>

#define BB 2
#define DD 10
#define HH 512
#define WW 512
#define HW (HH * WW)

__device__ __forceinline__ float4 fmax4(float4 a, float4 b) {
    return make_float4(fmaxf(a.x, b.x), fmaxf(a.y, b.y), fmaxf(a.z, b.z), fmaxf(a.w, b.w));
}

__global__ __launch_bounds__(256, 4)   // 64 regs, 4 CTAs/SM
void quadinterp3d_kernel(const float* __restrict__ x, float* __restrict__ out) {
    // Block = 2 complete W-rows (tid 0-127: h0, tid 128-255: h0+1); same (b,d) per block.
    __shared__ float sCmX[256], sCmW[256], sV4X[256], sV4W[256];
    __shared__ unsigned short q[512];   // (tid<<2 | j) codes of detected maxima
    __shared__ int qcnt;

    const int tid  = threadIdx.x;
    const int gid  = blockIdx.x * 256 + tid;
    const int lane = tid & 31;
    const int w4 = gid & 127;
    const int h  = (gid >> 7) & 511;
    const int t  = gid >> 16;            // 0..19 (B*D)
    const int d  = t % DD;
    const int b  = t / DD;
    const int w0 = w4 << 2;

    if (tid == 0) qcnt = 0;

    const int off4 = (d * HH + h) * WW;
    const float* __restrict__ base = x + (size_t)b * DD * HW;
    const float* __restrict__ pc = base + off4 + w0;

    // Clamped row deltas (replicate padding); dzm/dzp uniform per block
    const int dym = (h > 0)      ? WW : 0;
    const int dyp = (h < HH - 1) ? WW : 0;
    const int dzm = (d > 0)      ? HW : 0;
    const int dzp = (d < DD - 1) ? HW : 0;

    // Batched independent loads: one aligned float4 per stencil row (MLP=9)
    float4 v[9];
    v[0] = *reinterpret_cast<const float4*>(pc - dzm - dym);
    v[1] = *reinterpret_cast<const float4*>(pc - dzm);
    v[2] = *reinterpret_cast<const float4*>(pc - dzm + dyp);
    v[3] = *reinterpret_cast<const float4*>(pc - dym);
    v[4] = *reinterpret_cast<const float4*>(pc);
    v[5] = *reinterpret_cast<const float4*>(pc + dyp);
    v[6] = *reinterpret_cast<const float4*>(pc + dzp - dym);
    v[7] = *reinterpret_cast<const float4*>(pc + dzp);
    v[8] = *reinterpret_cast<const float4*>(pc + dzp + dym == 0 ? pc + dzp + dyp : pc + dzp + dyp);

    // (note: v[8] expression above is just pc + dzp + dyp)
    v[8] = *reinterpret_cast<const float4*>(pc + dzp + dyp);

    // Column max of the 8 non-center rows
    float4 cm = fmax4(fmax4(v[0], v[1]), fmax4(v[2], v[3]));
    cm = fmax4(cm, fmax4(fmax4(v[5], v[6]), fmax4(v[7], v[8])));

    // Block-level edge exchange
    sCmX[tid] = cm.x;  sCmW[tid] = cm.w;
    sV4X[tid] = v[4].x; sV4W[tid] = v[4].w;
    __syncthreads();

    const bool atL = (w4 == 0);
    const bool atR = (w4 == 127);
    const float cmL = atL ? cm.x   : sCmW[tid - 1];
    const float cmR = atR ? cm.w   : sCmX[tid + 1];
    const float u0  = atL ? v[4].x : sV4W[tid - 1];
    const float u5  = atR ? v[4].w : sV4X[tid + 1];

    // Windowed max over [cmL, cm.x, cm.y, cm.z, cm.w, cmR]
    const float win0 = fmaxf(fmaxf(cmL,  cm.x), cm.y);
    const float win1 = fmaxf(fmaxf(cm.x, cm.y), cm.z);
    const float win2 = fmaxf(fmaxf(cm.y, cm.z), cm.w);
    const float win3 = fmaxf(fmaxf(cm.z, cm.w), cmR);

    // Strict-local-max mask (center row excludes the center element)
    const float nm0 = fmaxf(fmaxf(win0, fmaxf(u0,     v[4].y)), 0.0f);
    const float nm1 = fmaxf(fmaxf(win1, fmaxf(v[4].x, v[4].z)), 0.0f);
    const float nm2 = fmaxf(fmaxf(win2, fmaxf(v[4].y, v[4].w)), 0.0f);
    const float nm3 = fmaxf(fmaxf(win3, fmaxf(v[4].z, u5)),     0.0f);

    const bool m0 = v[4].x > nm0;
    const bool m1 = v[4].y > nm1;
    const bool m2 = v[4].z > nm2;
    const bool m3 = v[4].w > nm3;

    // ---- Default stores (coords = grid, y = x). Ordered before queue phase
    //      by the __syncthreads below; queue threads overwrite maxima. ----
    const size_t plsz = (size_t)DD * HW;
    const size_t inner = (size_t)off4 + w0;
    const float fd = (float)d, fh = (float)h, fw = (float)w0;
    *reinterpret_cast<float4*>(out + (size_t)(b * 3 + 0) * plsz + inner) =
        make_float4(fd, fd, fd, fd);
    *reinterpret_cast<float4*>(out + (size_t)(b * 3 + 1) * plsz + inner) =
        make_float4(fh, fh, fh, fh);
    *reinterpret_cast<float4*>(out + (size_t)(b * 3 + 2) * plsz + inner) =
        make_float4(fw, fw + 1.0f, fw + 2.0f, fw + 3.0f);
    *reinterpret_cast<float4*>(out + (size_t)BB * 3 * plsz + (size_t)b * plsz + inner) = v[4];

    // ---- Warp-aggregated queue push: one shared atomic per warp ----
    const unsigned bal0 = __ballot_sync(0xffffffffu, m0);
    const unsigned bal1 = __ballot_sync(0xffffffffu, m1);
    const unsigned bal2 = __ballot_sync(0xffffffffu, m2);
    const unsigned bal3 = __ballot_sync(0xffffffffu, m3);
    const int nWarp = __popc(bal0) + __popc(bal1) + __popc(bal2) + __popc(bal3);
    int basei = 0;
    if (lane == 0 && nWarp) basei = atomicAdd(&qcnt, nWarp);
    basei = __shfl_sync(0xffffffffu, basei, 0);
    {
        const unsigned lm = (1u << lane) - 1u;
        int p = 0;
        if (m0) q[basei + __popc(bal0 & lm)] = (unsigned short)((tid << 2) | 0);
        p += __popc(bal0);
        if (m1) q[basei + p + __popc(bal1 & lm)] = (unsigned short)((tid << 2) | 1);
        p += __popc(bal1);
        if (m2) q[basei + p + __popc(bal2 & lm)] = (unsigned short)((tid << 2) | 2);
        p += __popc(bal2);
        if (m3) q[basei + p + __popc(bal3 & lm)] = (unsigned short)((tid << 2) | 3);
    }
    __syncthreads();

    // ---- Dense queue processing: each maximum handled by one thread.
    //      Inputs re-gathered via scalar __ldg (L1/L2 hits); v[] is dead here. ----
    const int cnt = qcnt;
    for (int i = tid; i < cnt; i += 256) {
        const int code = q[i];
        const int jj   = code & 3;
        const int otid = code >> 2;
        const int wq   = (((otid & 127) << 2) | jj);
        const int hq   = (blockIdx.x * 2 + (otid >> 7)) & 511;

        const float* __restrict__ pq = base + (d * HH + hq) * WW + wq;
        const int dl  = (wq > 0)      ? -1 : 0;
        const int dr  = (wq < WW - 1) ?  1 : 0;
        const int qym = (hq > 0)      ? WW : 0;
        const int qyp = (hq < HH - 1) ? WW : 0;

        // 19 stencil inputs (independent loads; compiler batches for MLP)
        const float cc = __ldg(pq);
        const float a4 = __ldg(pq + dl);
        const float c4 = __ldg(pq + dr);
        const float a3 = __ldg(pq - qym + dl);
        const float b3 = __ldg(pq - qym);
        const float c3 = __ldg(pq - qym + dr);
        const float a5 = __ldg(pq + qyp + dl);
        const float b5 = __ldg(pq + qyp);
        const float c5 = __ldg(pq + qyp + dr);
        const float a1 = __ldg(pq - dzm + dl);
        const float b1 = __ldg(pq - dzm);
        const float c1 = __ldg(pq - dzm + dr);
        const float a7 = __ldg(pq + dzp + dl);
        const float b7 = __ldg(pq + dzp);
        const float c7 = __ldg(pq + dzp + dr);
        const float e0 = __ldg(pq - dzm - qym);
        const float e2 = __ldg(pq - dzm + qyp);
        const float e6 = __ldg(pq + dzp - qym);
        const float e8 = __ldg(pq + dzp + qyp);

        // Newton solve (same algebra as the verified kernels; H symmetric)
        const float gx = 0.5f * (c4 - a4);
        const float gy = 0.5f * (b5 - b3);
        const float gs = 0.5f * (b7 - b1);

        const float h00 = a4 + c4 - 2.0f * cc;
        const float h11 = b3 + b5 - 2.0f * cc;
        const float h22 = b1 + b7 - 2.0f * cc;
        const float h01 = 0.25f * (a3 + c5 - a5 - c3);
        const float h12 = 0.25f * (e0 + e8 - e6 - e2);
        const float h02 = 0.25f * (a1 + c7 - a7 - c1);

        const float c00 = h11 * h22 - h12 * h12;
        const float c01 = h01 * h22 - h12 * h02;
        const float c02 = h01 * h12 - h11 * h02;
        const float det = h00 * c00 - h01 * c01 + h02 * c02;

        const float t1 = gy * h22 - h12 * gs;
        const float t2 = gy * h12 - h11 * gs;
        const float t3 = h01 * gs - gy * h02;

        const float inv = 1.0f / det;
        const float sx = (gx * c00 - h01 * t1 + h02 * t2) * inv;
        const float sy = (h00 * t1 - gx * c01 + h02 * t3) * inv;
        const float ss = (h00 * (h11 * gs - h12 * gy) - h01 * t3 + gx * c02) * inv;

        float d0 = -sx, d1 = -sy, d2 = -ss;
        const float far = fmaxf(fmaxf(fabsf(d0), fabsf(d1)), fabsf(d2));
        if (far > 0.7f) { d0 = 0.0f; d1 = 0.0f; d2 = 0.0f; }

        const float ry = cc + 0.5f * (gx * d0 + gy * d1 + gs * d2) + 10.0f;

        const size_t innq = (size_t)(d * HH + hq) * WW + wq;
        out[(size_t)(b * 3 + 0) * plsz + innq] = (float)d  + d2;
        out[(size_t)(b * 3 + 1) * plsz + innq] = (float)hq + d1;
        out[(size_t)(b * 3 + 2) * plsz + innq] = (float)wq + d0;
        out[(size_t)BB * 3 * plsz + (size_t)b * plsz + innq] = ry;
    }
}

extern "C" void kernel_launch(void* const* d_in, const int* in_sizes, int n_in,
                              void* d_out, int out_size) {
    const float* x = (const float*)d_in[0];
    float* out = (float*)d_out;
    const int total_threads = BB * DD * HH * (WW / 4);   // 1,310,720
    const int block = 256;
    const int grid = total_threads / block;              // 5,120
    quadinterp3d_kernel<<<grid, block>>>(x, out);
}